// round 13
// baseline (speedup 1.0000x reference)
#include <cuda_runtime.h>
#include <cuda_fp16.h>
#include <cstdint>
#include <cstddef>

// x = [u*m, u, m] (96) ; h = relu(x @ w1^T + b1) (8) ; out = sigmoid(h @ w2^T + b2)
// D = X@W1^T via mma.sync.m16n8k16 fp16 (fp32 accum).
// Layout (R12): rows interleave u/m in 16B units [u0 m0 u1 m1 ...]; STS 2-phase
// minimal; LDSM conflict-free; um a-frags = hmul2(u,m); b-frag k-steps 0..3
// carry 1/64 scaling.
// R13: 224-thread / 224-element CTAs -> 6 CTAs/SM (regs 48*224*6 = 64512,
// smem 6*33.9KB = 203.5KB) = 42 warps/SM vs 40, finer wave granularity.

#define NTHREADS 224
#define NWARPS 7
#define ELTS 224
#define ROWB 144            // 8 x 16B units + 16B pad (odd multiple of 16)
#define U_SCALE 64.0f
#define U_INV (1.0f / 64.0f)

#define XS_BYTES (ELTS * ROWB)        // 32256
#define FRAG_OFF XS_BYTES             // uint32_t[384]: [lane][12]
#define BIAS_OFF (FRAG_OFF + 1536)    // float[17]
#define SMEM_TOTAL (BIAS_OFF + 128)   // 33920 -> 6 CTAs/SM

__device__ __forceinline__ float4 ldg_na128(const float* p) {
    float4 v;
    asm volatile("ld.global.L1::no_allocate.v4.f32 {%0,%1,%2,%3}, [%4];"
                 : "=f"(v.x), "=f"(v.y), "=f"(v.z), "=f"(v.w) : "l"(p));
    return v;
}

__device__ __forceinline__ uint32_t packh2(float a, float b) {
    __half2 h = __floats2half2_rn(a, b);
    return *(uint32_t*)&h;
}

__device__ __forceinline__ uint32_t hmul2u(uint32_t a, uint32_t b) {
    __half2 r = __hmul2(*(__half2*)&a, *(__half2*)&b);
    return *(uint32_t*)&r;
}

__device__ __forceinline__ void mma_f16(float* c, uint32_t a0, uint32_t a1,
                                        uint32_t a2, uint32_t a3,
                                        uint32_t b0, uint32_t b1) {
    asm volatile(
        "mma.sync.aligned.m16n8k16.row.col.f32.f16.f16.f32 "
        "{%0,%1,%2,%3}, {%4,%5,%6,%7}, {%8,%9}, {%0,%1,%2,%3};"
        : "+f"(c[0]), "+f"(c[1]), "+f"(c[2]), "+f"(c[3])
        : "r"(a0), "r"(a1), "r"(a2), "r"(a3), "r"(b0), "r"(b1));
}

__device__ __forceinline__ void ldsm4(uint32_t* r, uint32_t addr) {
    asm volatile("ldmatrix.sync.aligned.m8n8.x4.shared.b16 {%0,%1,%2,%3}, [%4];"
                 : "=r"(r[0]), "=r"(r[1]), "=r"(r[2]), "=r"(r[3]) : "r"(addr));
}

__global__ __launch_bounds__(NTHREADS, 6)
void neuralnet_mma16j_kernel(const int* __restrict__ users,
                             const int* __restrict__ movies,
                             const float* __restrict__ user_emb,
                             const float* __restrict__ movie_emb,
                             const float* __restrict__ w1,
                             const float* __restrict__ b1,
                             const float* __restrict__ w2,
                             const float* __restrict__ b2,
                             float* __restrict__ out,
                             int n) {
    extern __shared__ __align__(16) char Xs[];
    uint32_t* fragS = (uint32_t*)(Xs + FRAG_OFF);
    float* biasS = (float*)(Xs + BIAS_OFF);

    const unsigned FULL = 0xffffffffu;
    const int tid = threadIdx.x;
    const int l = tid & 31;
    const int w = tid >> 5;
    const int blockBase = blockIdx.x * ELTS;
    char* xwarp = Xs + (size_t)(w << 5) * ROWB;

    // ---- per-CTA b-frag table: threads 0..127 pack 3 slots each ----
    if (tid < 128) {
#pragma unroll
        for (int r = 0; r < 3; ++r) {
            const int g = 3 * tid + r;
            const int L = g / 12, q = g - 12 * L;
            const int s = (q >= 6) ? q - 6 : q;
            const int k0 = 16 * s + 2 * (L & 3) + ((q >= 6) ? 8 : 0);
            const float sc = (s < 4) ? U_INV : 1.0f;
            const float* wr = w1 + (L >> 2) * 96 + k0;
            fragS[g] = packh2(__ldg(wr) * sc, __ldg(wr + 1) * sc);
        }
    } else if (tid < 136) {
        const int i = tid - 128;
        biasS[i] = __ldg(&b1[i]);
        biasS[8 + i] = __ldg(&w2[i]);
        if (i == 0) biasS[16] = __ldg(&b2[0]);
    }
    __syncthreads();   // early, uniform convergence point

    // ---- cooperative coalesced gather, 4-deep pipeline (MLP=8) ----
    int eg = blockBase + (w << 5) + l;
    int ec = (eg < n) ? eg : (n - 1);
    const int uidx = users[ec];
    const int midx = movies[ec];

    const int chunk = l & 7;
    const int esub = l >> 3;
    const float* uC = user_emb + (chunk << 2);
    const float* mC = movie_emb + (chunk << 2);
    // interleaved destination: u 8B at 32*(c>>1) + 8*(c&1); m at +16
    const uint32_t uoff = (uint32_t)(((chunk >> 1) << 5) + ((chunk & 1) << 3));

    {
        float4 ub[4], mb[4];
#pragma unroll
        for (int i = 0; i < 4; ++i) {
            const int src = 4 * i + esub;
            const int ue = __shfl_sync(FULL, uidx, src);
            const int me = __shfl_sync(FULL, midx, src);
            ub[i] = ldg_na128(uC + (size_t)ue * 32);
            mb[i] = ldg_na128(mC + (size_t)me * 32);
        }
#pragma unroll
        for (int i = 0; i < 8; ++i) {
            const float4 u4 = ub[i & 3];
            const float4 m4 = mb[i & 3];
            if (i < 4) {
                const int src = 4 * (i + 4) + esub;
                const int ue = __shfl_sync(FULL, uidx, src);
                const int me = __shfl_sync(FULL, midx, src);
                ub[i & 3] = ldg_na128(uC + (size_t)ue * 32);
                mb[i & 3] = ldg_na128(mC + (size_t)me * 32);
            }
            char* xr = xwarp + (size_t)(4 * i + esub) * ROWB + uoff;
            *(uint2*)(xr) = make_uint2(packh2(u4.x * U_SCALE, u4.y * U_SCALE),
                                       packh2(u4.z * U_SCALE, u4.w * U_SCALE));
            *(uint2*)(xr + 16) = make_uint2(packh2(m4.x, m4.y), packh2(m4.z, m4.w));
        }
    }
    __syncwarp();   // warp-private tile

    // ---- per-thread frags (3 conflict-free LDS.128), AFTER gather ----
    uint32_t B0[6], B1[6];
    {
        const uint4* fp = (const uint4*)(fragS + l * 12);
        uint4 F0 = fp[0], F1 = fp[1], F2 = fp[2];
        B0[0] = F0.x; B0[1] = F0.y; B0[2] = F0.z; B0[3] = F0.w;
        B0[4] = F1.x; B0[5] = F1.y; B1[0] = F1.z; B1[1] = F1.w;
        B1[2] = F2.x; B1[3] = F2.y; B1[4] = F2.z; B1[5] = F2.w;
    }

    // ---- GEMM: 2 m-tiles; frags from interleaved layout ----
    // phys units: u_t at 32t, m_t at 32t+16 -> half-warp stride 32.
    const uint32_t xs = (uint32_t)__cvta_generic_to_shared(xwarp);
    float acc[2][4] = {{0.f, 0.f, 0.f, 0.f}, {0.f, 0.f, 0.f, 0.f}};

#pragma unroll
    for (int t = 0; t < 2; ++t) {
        const uint32_t abase = xs + (uint32_t)((t * 16 + (l & 15)) * ROWB)
                             + (uint32_t)((l >> 4) << 5);
        uint32_t U[2][4], M[2][4];
        ldsm4(U[0], abase);          // u units 0,1 (cols 0..15)
        ldsm4(U[1], abase + 64);     // u units 2,3 (cols 16..31)
        ldsm4(M[0], abase + 16);     // m units 0,1
        ldsm4(M[1], abase + 80);     // m units 2,3

        uint32_t P[4];
#pragma unroll
        for (int j = 0; j < 4; ++j) P[j] = hmul2u(U[0][j], M[0][j]);
        mma_f16(acc[t], P[0], P[1], P[2], P[3], B0[0], B1[0]);
#pragma unroll
        for (int j = 0; j < 4; ++j) P[j] = hmul2u(U[1][j], M[1][j]);
        mma_f16(acc[t], P[0], P[1], P[2], P[3], B0[1], B1[1]);

        mma_f16(acc[t], U[0][0], U[0][1], U[0][2], U[0][3], B0[2], B1[2]);
        mma_f16(acc[t], U[1][0], U[1][1], U[1][2], U[1][3], B0[3], B1[3]);
        mma_f16(acc[t], M[0][0], M[0][1], M[0][2], M[0][3], B0[4], B1[4]);
        mma_f16(acc[t], M[1][0], M[1][1], M[1][2], M[1][3], B0[5], B1[5]);
    }

    // ---- epilogue ----
    const int bk = l & 3;
    const float b1a = biasS[2 * bk];
    const float b1b = biasS[2 * bk + 1];
    const float w2a = biasS[8 + 2 * bk];
    const float w2b = biasS[9 + 2 * bk];
    const float bb2 = biasS[16];

#pragma unroll
    for (int t = 0; t < 2; ++t) {
        float z0 = fmaxf(acc[t][0] + b1a, 0.f) * w2a +
                   fmaxf(acc[t][1] + b1b, 0.f) * w2b;
        float z1 = fmaxf(acc[t][2] + b1a, 0.f) * w2a +
                   fmaxf(acc[t][3] + b1b, 0.f) * w2b;
        z0 += __shfl_xor_sync(FULL, z0, 1);
        z0 += __shfl_xor_sync(FULL, z0, 2);
        z1 += __shfl_xor_sync(FULL, z1, 1);
        z1 += __shfl_xor_sync(FULL, z1, 2);
        if (bk == 0) {
            const int e0 = blockBase + (w << 5) + t * 16 + (l >> 2);
            if (e0 < n) out[e0] = 1.0f / (1.0f + __expf(-(z0 + bb2)));
            const int e1 = e0 + 8;
            if (e1 < n) out[e1] = 1.0f / (1.0f + __expf(-(z1 + bb2)));
        }
    }
}

extern "C" void kernel_launch(void* const* d_in, const int* in_sizes, int n_in,
                              void* d_out, int out_size) {
    const int*   users     = (const int*)d_in[0];
    const int*   movies    = (const int*)d_in[1];
    const float* user_emb  = (const float*)d_in[2];
    const float* movie_emb = (const float*)d_in[3];
    const float* w1        = (const float*)d_in[4];
    const float* b1        = (const float*)d_in[5];
    const float* w2        = (const float*)d_in[6];
    const float* b2        = (const float*)d_in[7];
    int n = in_sizes[0];

    static bool attr_set = false;
    if (!attr_set) {
        cudaFuncSetAttribute(neuralnet_mma16j_kernel,
                             cudaFuncAttributeMaxDynamicSharedMemorySize, SMEM_TOTAL);
        attr_set = true;
    }
    int blocks = (n + ELTS - 1) / ELTS;
    neuralnet_mma16j_kernel<<<blocks, NTHREADS, SMEM_TOTAL>>>(
        users, movies, user_emb, movie_emb, w1, b1, w2, b2, (float*)d_out, n);
}

// round 14
// speedup vs baseline: 1.6274x; 1.6274x over previous
#include <cuda_runtime.h>
#include <cuda_fp16.h>
#include <cstdint>
#include <cstddef>

// x = [u*m, u, m] (96) ; h = relu(x @ w1^T + b1) (8) ; out = sigmoid(h @ w2^T + b2)
// D = X@W1^T via mma.sync.m16n8k16 fp16 (fp32 accum).
// Layout (R12): rows interleave u/m in 16B units [u0 m0 u1 m1 ...]; STS 2-phase
// minimal; LDSM conflict-free; um a-frags = hmul2(u,m); b-frag k-steps 0..3
// carry 1/64 scaling.
// R14: 224 threads with __launch_bounds__(224, 5) -- ptxas budget 58 regs so
// the R12-identical body keeps its 48-reg allocation (R13's minBlocks=6 forced
// 40 regs and broke the gather pipeline). 48*224 = 10752 regs/CTA -> hardware
// fits 6 CTAs/SM (64512 regs, 203.5KB smem) = 42 warps/SM.

#define NTHREADS 224
#define ELTS 224
#define ROWB 144            // 8 x 16B units + 16B pad (odd multiple of 16)
#define U_SCALE 64.0f
#define U_INV (1.0f / 64.0f)

#define XS_BYTES (ELTS * ROWB)        // 32256
#define FRAG_OFF XS_BYTES             // uint32_t[384]: [lane][12]
#define BIAS_OFF (FRAG_OFF + 1536)    // float[17]
#define SMEM_TOTAL (BIAS_OFF + 128)   // 33920 -> 6 CTAs/SM at 48 regs

__device__ __forceinline__ float4 ldg_na128(const float* p) {
    float4 v;
    asm volatile("ld.global.L1::no_allocate.v4.f32 {%0,%1,%2,%3}, [%4];"
                 : "=f"(v.x), "=f"(v.y), "=f"(v.z), "=f"(v.w) : "l"(p));
    return v;
}

__device__ __forceinline__ uint32_t packh2(float a, float b) {
    __half2 h = __floats2half2_rn(a, b);
    return *(uint32_t*)&h;
}

__device__ __forceinline__ uint32_t hmul2u(uint32_t a, uint32_t b) {
    __half2 r = __hmul2(*(__half2*)&a, *(__half2*)&b);
    return *(uint32_t*)&r;
}

__device__ __forceinline__ void mma_f16(float* c, uint32_t a0, uint32_t a1,
                                        uint32_t a2, uint32_t a3,
                                        uint32_t b0, uint32_t b1) {
    asm volatile(
        "mma.sync.aligned.m16n8k16.row.col.f32.f16.f16.f32 "
        "{%0,%1,%2,%3}, {%4,%5,%6,%7}, {%8,%9}, {%0,%1,%2,%3};"
        : "+f"(c[0]), "+f"(c[1]), "+f"(c[2]), "+f"(c[3])
        : "r"(a0), "r"(a1), "r"(a2), "r"(a3), "r"(b0), "r"(b1));
}

__device__ __forceinline__ void ldsm4(uint32_t* r, uint32_t addr) {
    asm volatile("ldmatrix.sync.aligned.m8n8.x4.shared.b16 {%0,%1,%2,%3}, [%4];"
                 : "=r"(r[0]), "=r"(r[1]), "=r"(r[2]), "=r"(r[3]) : "r"(addr));
}

__global__ __launch_bounds__(NTHREADS, 5)
void neuralnet_mma16k_kernel(const int* __restrict__ users,
                             const int* __restrict__ movies,
                             const float* __restrict__ user_emb,
                             const float* __restrict__ movie_emb,
                             const float* __restrict__ w1,
                             const float* __restrict__ b1,
                             const float* __restrict__ w2,
                             const float* __restrict__ b2,
                             float* __restrict__ out,
                             int n) {
    extern __shared__ __align__(16) char Xs[];
    uint32_t* fragS = (uint32_t*)(Xs + FRAG_OFF);
    float* biasS = (float*)(Xs + BIAS_OFF);

    const unsigned FULL = 0xffffffffu;
    const int tid = threadIdx.x;
    const int l = tid & 31;
    const int w = tid >> 5;
    const int blockBase = blockIdx.x * ELTS;
    char* xwarp = Xs + (size_t)(w << 5) * ROWB;

    // ---- per-CTA b-frag table: threads 0..127 pack 3 slots each ----
    if (tid < 128) {
#pragma unroll
        for (int r = 0; r < 3; ++r) {
            const int g = 3 * tid + r;
            const int L = g / 12, q = g - 12 * L;
            const int s = (q >= 6) ? q - 6 : q;
            const int k0 = 16 * s + 2 * (L & 3) + ((q >= 6) ? 8 : 0);
            const float sc = (s < 4) ? U_INV : 1.0f;
            const float* wr = w1 + (L >> 2) * 96 + k0;
            fragS[g] = packh2(__ldg(wr) * sc, __ldg(wr + 1) * sc);
        }
    } else if (tid < 136) {
        const int i = tid - 128;
        biasS[i] = __ldg(&b1[i]);
        biasS[8 + i] = __ldg(&w2[i]);
        if (i == 0) biasS[16] = __ldg(&b2[0]);
    }
    __syncthreads();   // early, uniform convergence point

    // ---- cooperative coalesced gather, 4-deep pipeline (MLP=8) ----
    int eg = blockBase + (w << 5) + l;
    int ec = (eg < n) ? eg : (n - 1);
    const int uidx = users[ec];
    const int midx = movies[ec];

    const int chunk = l & 7;
    const int esub = l >> 3;
    const float* uC = user_emb + (chunk << 2);
    const float* mC = movie_emb + (chunk << 2);
    // interleaved destination: u 8B at 32*(c>>1) + 8*(c&1); m at +16
    const uint32_t uoff = (uint32_t)(((chunk >> 1) << 5) + ((chunk & 1) << 3));

    {
        float4 ub[4], mb[4];
#pragma unroll
        for (int i = 0; i < 4; ++i) {
            const int src = 4 * i + esub;
            const int ue = __shfl_sync(FULL, uidx, src);
            const int me = __shfl_sync(FULL, midx, src);
            ub[i] = ldg_na128(uC + (size_t)ue * 32);
            mb[i] = ldg_na128(mC + (size_t)me * 32);
        }
#pragma unroll
        for (int i = 0; i < 8; ++i) {
            const float4 u4 = ub[i & 3];
            const float4 m4 = mb[i & 3];
            if (i < 4) {
                const int src = 4 * (i + 4) + esub;
                const int ue = __shfl_sync(FULL, uidx, src);
                const int me = __shfl_sync(FULL, midx, src);
                ub[i & 3] = ldg_na128(uC + (size_t)ue * 32);
                mb[i & 3] = ldg_na128(mC + (size_t)me * 32);
            }
            char* xr = xwarp + (size_t)(4 * i + esub) * ROWB + uoff;
            *(uint2*)(xr) = make_uint2(packh2(u4.x * U_SCALE, u4.y * U_SCALE),
                                       packh2(u4.z * U_SCALE, u4.w * U_SCALE));
            *(uint2*)(xr + 16) = make_uint2(packh2(m4.x, m4.y), packh2(m4.z, m4.w));
        }
    }
    __syncwarp();   // warp-private tile

    // ---- per-thread frags (3 conflict-free LDS.128), AFTER gather ----
    uint32_t B0[6], B1[6];
    {
        const uint4* fp = (const uint4*)(fragS + l * 12);
        uint4 F0 = fp[0], F1 = fp[1], F2 = fp[2];
        B0[0] = F0.x; B0[1] = F0.y; B0[2] = F0.z; B0[3] = F0.w;
        B0[4] = F1.x; B0[5] = F1.y; B1[0] = F1.z; B1[1] = F1.w;
        B1[2] = F2.x; B1[3] = F2.y; B1[4] = F2.z; B1[5] = F2.w;
    }

    // ---- GEMM: 2 m-tiles; frags from interleaved layout ----
    // phys units: u_t at 32t, m_t at 32t+16 -> half-warp stride 32.
    const uint32_t xs = (uint32_t)__cvta_generic_to_shared(xwarp);
    float acc[2][4] = {{0.f, 0.f, 0.f, 0.f}, {0.f, 0.f, 0.f, 0.f}};

#pragma unroll
    for (int t = 0; t < 2; ++t) {
        const uint32_t abase = xs + (uint32_t)((t * 16 + (l & 15)) * ROWB)
                             + (uint32_t)((l >> 4) << 5);
        uint32_t U[2][4], M[2][4];
        ldsm4(U[0], abase);          // u units 0,1 (cols 0..15)
        ldsm4(U[1], abase + 64);     // u units 2,3 (cols 16..31)
        ldsm4(M[0], abase + 16);     // m units 0,1
        ldsm4(M[1], abase + 80);     // m units 2,3

        uint32_t P[4];
#pragma unroll
        for (int j = 0; j < 4; ++j) P[j] = hmul2u(U[0][j], M[0][j]);
        mma_f16(acc[t], P[0], P[1], P[2], P[3], B0[0], B1[0]);
#pragma unroll
        for (int j = 0; j < 4; ++j) P[j] = hmul2u(U[1][j], M[1][j]);
        mma_f16(acc[t], P[0], P[1], P[2], P[3], B0[1], B1[1]);

        mma_f16(acc[t], U[0][0], U[0][1], U[0][2], U[0][3], B0[2], B1[2]);
        mma_f16(acc[t], U[1][0], U[1][1], U[1][2], U[1][3], B0[3], B1[3]);
        mma_f16(acc[t], M[0][0], M[0][1], M[0][2], M[0][3], B0[4], B1[4]);
        mma_f16(acc[t], M[1][0], M[1][1], M[1][2], M[1][3], B0[5], B1[5]);
    }

    // ---- epilogue ----
    const int bk = l & 3;
    const float b1a = biasS[2 * bk];
    const float b1b = biasS[2 * bk + 1];
    const float w2a = biasS[8 + 2 * bk];
    const float w2b = biasS[9 + 2 * bk];
    const float bb2 = biasS[16];

#pragma unroll
    for (int t = 0; t < 2; ++t) {
        float z0 = fmaxf(acc[t][0] + b1a, 0.f) * w2a +
                   fmaxf(acc[t][1] + b1b, 0.f) * w2b;
        float z1 = fmaxf(acc[t][2] + b1a, 0.f) * w2a +
                   fmaxf(acc[t][3] + b1b, 0.f) * w2b;
        z0 += __shfl_xor_sync(FULL, z0, 1);
        z0 += __shfl_xor_sync(FULL, z0, 2);
        z1 += __shfl_xor_sync(FULL, z1, 1);
        z1 += __shfl_xor_sync(FULL, z1, 2);
        if (bk == 0) {
            const int e0 = blockBase + (w << 5) + t * 16 + (l >> 2);
            if (e0 < n) out[e0] = 1.0f / (1.0f + __expf(-(z0 + bb2)));
            const int e1 = e0 + 8;
            if (e1 < n) out[e1] = 1.0f / (1.0f + __expf(-(z1 + bb2)));
        }
    }
}

extern "C" void kernel_launch(void* const* d_in, const int* in_sizes, int n_in,
                              void* d_out, int out_size) {
    const int*   users     = (const int*)d_in[0];
    const int*   movies    = (const int*)d_in[1];
    const float* user_emb  = (const float*)d_in[2];
    const float* movie_emb = (const float*)d_in[3];
    const float* w1        = (const float*)d_in[4];
    const float* b1        = (const float*)d_in[5];
    const float* w2        = (const float*)d_in[6];
    const float* b2        = (const float*)d_in[7];
    int n = in_sizes[0];

    static bool attr_set = false;
    if (!attr_set) {
        cudaFuncSetAttribute(neuralnet_mma16k_kernel,
                             cudaFuncAttributeMaxDynamicSharedMemorySize, SMEM_TOTAL);
        attr_set = true;
    }
    int blocks = (n + ELTS - 1) / ELTS;
    neuralnet_mma16k_kernel<<<blocks, NTHREADS, SMEM_TOTAL>>>(
        users, movies, user_emb, movie_emb, w1, b1, w2, b2, (float*)d_out, n);
}

// round 15
// speedup vs baseline: 1.7318x; 1.0642x over previous
#include <cuda_runtime.h>
#include <cuda_fp16.h>
#include <cstdint>
#include <cstddef>

// x = [u*m, u, m] (96) ; h = relu(x @ w1^T + b1) (8) ; out = sigmoid(h @ w2^T + b2)
// D = X@W1^T via mma.sync.m16n8k16 fp16 (fp32 accum).
// Layout (R12, best): rows interleave u/m in 16B units [u0 m0 u1 m1 ...];
// STS 2-phase minimal; LDSM conflict-free; um a-frags = hmul2(u,m); b-frag
// k-steps 0..3 carry 1/64 scaling. 256 thr, minBlocks=5 -> 48 regs, 5 CTAs/SM.
// R15: b-frag table build now two-stage -- w1 staged into SMEM with 192
// coalesced LDG.128 (24 wf/CTA vs ~100 wf of scattered LDG.32, ~8% of CTA
// l1tex work), frags computed from the staged copy. Staging aliases the X
// area (dead until gather); one extra early __syncthreads.

#define NTHREADS 256
#define ELTS 256
#define ROWB 144            // 8 x 16B units + 16B pad (odd multiple of 16)
#define U_SCALE 64.0f
#define U_INV (1.0f / 64.0f)

#define XS_BYTES (ELTS * ROWB)        // 36864
#define FRAG_OFF XS_BYTES             // uint32_t[384]: [lane][12]
#define BIAS_OFF (FRAG_OFF + 1536)    // float[17]
#define SMEM_TOTAL (BIAS_OFF + 128)   // 38528 -> 5 CTAs/SM

__device__ __forceinline__ float4 ldg_na128(const float* p) {
    float4 v;
    asm volatile("ld.global.L1::no_allocate.v4.f32 {%0,%1,%2,%3}, [%4];"
                 : "=f"(v.x), "=f"(v.y), "=f"(v.z), "=f"(v.w) : "l"(p));
    return v;
}

__device__ __forceinline__ uint32_t packh2(float a, float b) {
    __half2 h = __floats2half2_rn(a, b);
    return *(uint32_t*)&h;
}

__device__ __forceinline__ uint32_t hmul2u(uint32_t a, uint32_t b) {
    __half2 r = __hmul2(*(__half2*)&a, *(__half2*)&b);
    return *(uint32_t*)&r;
}

__device__ __forceinline__ void mma_f16(float* c, uint32_t a0, uint32_t a1,
                                        uint32_t a2, uint32_t a3,
                                        uint32_t b0, uint32_t b1) {
    asm volatile(
        "mma.sync.aligned.m16n8k16.row.col.f32.f16.f16.f32 "
        "{%0,%1,%2,%3}, {%4,%5,%6,%7}, {%8,%9}, {%0,%1,%2,%3};"
        : "+f"(c[0]), "+f"(c[1]), "+f"(c[2]), "+f"(c[3])
        : "r"(a0), "r"(a1), "r"(a2), "r"(a3), "r"(b0), "r"(b1));
}

__device__ __forceinline__ void ldsm4(uint32_t* r, uint32_t addr) {
    asm volatile("ldmatrix.sync.aligned.m8n8.x4.shared.b16 {%0,%1,%2,%3}, [%4];"
                 : "=r"(r[0]), "=r"(r[1]), "=r"(r[2]), "=r"(r[3]) : "r"(addr));
}

__global__ __launch_bounds__(NTHREADS, 5)
void neuralnet_mma16m_kernel(const int* __restrict__ users,
                             const int* __restrict__ movies,
                             const float* __restrict__ user_emb,
                             const float* __restrict__ movie_emb,
                             const float* __restrict__ w1,
                             const float* __restrict__ b1,
                             const float* __restrict__ w2,
                             const float* __restrict__ b2,
                             float* __restrict__ out,
                             int n) {
    extern __shared__ __align__(16) char Xs[];
    uint32_t* fragS = (uint32_t*)(Xs + FRAG_OFF);
    float* biasS = (float*)(Xs + BIAS_OFF);
    float* stageW = (float*)Xs;            // w1 staging, aliases X area (dead now)

    const unsigned FULL = 0xffffffffu;
    const int tid = threadIdx.x;
    const int l = tid & 31;
    const int w = tid >> 5;
    const int blockBase = blockIdx.x * ELTS;
    char* xwarp = Xs + (size_t)(w << 5) * ROWB;

    // ---- stage 1: coalesced copy of w1 (768 floats = 192 float4) + biases ----
    if (tid < 192) {
        ((float4*)stageW)[tid] = ((const float4*)w1)[tid];
    } else if (tid < 200) {
        const int i = tid - 192;
        biasS[i] = __ldg(&b1[i]);
        biasS[8 + i] = __ldg(&w2[i]);
        if (i == 0) biasS[16] = __ldg(&b2[0]);
    }
    __syncthreads();

    // ---- stage 2: build frag table from staged w1 (SMEM reads) ----
    if (tid < 128) {
#pragma unroll
        for (int r = 0; r < 3; ++r) {
            const int g = 3 * tid + r;
            const int L = g / 12, q = g - 12 * L;
            const int s = (q >= 6) ? q - 6 : q;
            const int k0 = 16 * s + 2 * (L & 3) + ((q >= 6) ? 8 : 0);
            const float sc = (s < 4) ? U_INV : 1.0f;
            const float* wr = stageW + (L >> 2) * 96 + k0;
            fragS[g] = packh2(wr[0] * sc, wr[1] * sc);
        }
    }
    __syncthreads();   // fragS complete; staging area may now be overwritten

    // ---- cooperative coalesced gather, 4-deep pipeline (MLP=8) ----
    int eg = blockBase + (w << 5) + l;
    int ec = (eg < n) ? eg : (n - 1);
    const int uidx = users[ec];
    const int midx = movies[ec];

    const int chunk = l & 7;
    const int esub = l >> 3;
    const float* uC = user_emb + (chunk << 2);
    const float* mC = movie_emb + (chunk << 2);
    // interleaved destination: u 8B at 32*(c>>1) + 8*(c&1); m at +16
    const uint32_t uoff = (uint32_t)(((chunk >> 1) << 5) + ((chunk & 1) << 3));

    {
        float4 ub[4], mb[4];
#pragma unroll
        for (int i = 0; i < 4; ++i) {
            const int src = 4 * i + esub;
            const int ue = __shfl_sync(FULL, uidx, src);
            const int me = __shfl_sync(FULL, midx, src);
            ub[i] = ldg_na128(uC + (size_t)ue * 32);
            mb[i] = ldg_na128(mC + (size_t)me * 32);
        }
#pragma unroll
        for (int i = 0; i < 8; ++i) {
            const float4 u4 = ub[i & 3];
            const float4 m4 = mb[i & 3];
            if (i < 4) {
                const int src = 4 * (i + 4) + esub;
                const int ue = __shfl_sync(FULL, uidx, src);
                const int me = __shfl_sync(FULL, midx, src);
                ub[i & 3] = ldg_na128(uC + (size_t)ue * 32);
                mb[i & 3] = ldg_na128(mC + (size_t)me * 32);
            }
            char* xr = xwarp + (size_t)(4 * i + esub) * ROWB + uoff;
            *(uint2*)(xr) = make_uint2(packh2(u4.x * U_SCALE, u4.y * U_SCALE),
                                       packh2(u4.z * U_SCALE, u4.w * U_SCALE));
            *(uint2*)(xr + 16) = make_uint2(packh2(m4.x, m4.y), packh2(m4.z, m4.w));
        }
    }
    __syncwarp();   // warp-private tile

    // ---- per-thread frags (3 conflict-free LDS.128), AFTER gather ----
    uint32_t B0[6], B1[6];
    {
        const uint4* fp = (const uint4*)(fragS + l * 12);
        uint4 F0 = fp[0], F1 = fp[1], F2 = fp[2];
        B0[0] = F0.x; B0[1] = F0.y; B0[2] = F0.z; B0[3] = F0.w;
        B0[4] = F1.x; B0[5] = F1.y; B1[0] = F1.z; B1[1] = F1.w;
        B1[2] = F2.x; B1[3] = F2.y; B1[4] = F2.z; B1[5] = F2.w;
    }

    // ---- GEMM: 2 m-tiles; frags from interleaved layout ----
    // phys units: u_t at 32t, m_t at 32t+16 -> half-warp stride 32.
    const uint32_t xs = (uint32_t)__cvta_generic_to_shared(xwarp);
    float acc[2][4] = {{0.f, 0.f, 0.f, 0.f}, {0.f, 0.f, 0.f, 0.f}};

#pragma unroll
    for (int t = 0; t < 2; ++t) {
        const uint32_t abase = xs + (uint32_t)((t * 16 + (l & 15)) * ROWB)
                             + (uint32_t)((l >> 4) << 5);
        uint32_t U[2][4], M[2][4];
        ldsm4(U[0], abase);          // u units 0,1 (cols 0..15)
        ldsm4(U[1], abase + 64);     // u units 2,3 (cols 16..31)
        ldsm4(M[0], abase + 16);     // m units 0,1
        ldsm4(M[1], abase + 80);     // m units 2,3

        uint32_t P[4];
#pragma unroll
        for (int j = 0; j < 4; ++j) P[j] = hmul2u(U[0][j], M[0][j]);
        mma_f16(acc[t], P[0], P[1], P[2], P[3], B0[0], B1[0]);
#pragma unroll
        for (int j = 0; j < 4; ++j) P[j] = hmul2u(U[1][j], M[1][j]);
        mma_f16(acc[t], P[0], P[1], P[2], P[3], B0[1], B1[1]);

        mma_f16(acc[t], U[0][0], U[0][1], U[0][2], U[0][3], B0[2], B1[2]);
        mma_f16(acc[t], U[1][0], U[1][1], U[1][2], U[1][3], B0[3], B1[3]);
        mma_f16(acc[t], M[0][0], M[0][1], M[0][2], M[0][3], B0[4], B1[4]);
        mma_f16(acc[t], M[1][0], M[1][1], M[1][2], M[1][3], B0[5], B1[5]);
    }

    // ---- epilogue ----
    const int bk = l & 3;
    const float b1a = biasS[2 * bk];
    const float b1b = biasS[2 * bk + 1];
    const float w2a = biasS[8 + 2 * bk];
    const float w2b = biasS[9 + 2 * bk];
    const float bb2 = biasS[16];

#pragma unroll
    for (int t = 0; t < 2; ++t) {
        float z0 = fmaxf(acc[t][0] + b1a, 0.f) * w2a +
                   fmaxf(acc[t][1] + b1b, 0.f) * w2b;
        float z1 = fmaxf(acc[t][2] + b1a, 0.f) * w2a +
                   fmaxf(acc[t][3] + b1b, 0.f) * w2b;
        z0 += __shfl_xor_sync(FULL, z0, 1);
        z0 += __shfl_xor_sync(FULL, z0, 2);
        z1 += __shfl_xor_sync(FULL, z1, 1);
        z1 += __shfl_xor_sync(FULL, z1, 2);
        if (bk == 0) {
            const int e0 = blockBase + (w << 5) + t * 16 + (l >> 2);
            if (e0 < n) out[e0] = 1.0f / (1.0f + __expf(-(z0 + bb2)));
            const int e1 = e0 + 8;
            if (e1 < n) out[e1] = 1.0f / (1.0f + __expf(-(z1 + bb2)));
        }
    }
}

extern "C" void kernel_launch(void* const* d_in, const int* in_sizes, int n_in,
                              void* d_out, int out_size) {
    const int*   users     = (const int*)d_in[0];
    const int*   movies    = (const int*)d_in[1];
    const float* user_emb  = (const float*)d_in[2];
    const float* movie_emb = (const float*)d_in[3];
    const float* w1        = (const float*)d_in[4];
    const float* b1        = (const float*)d_in[5];
    const float* w2        = (const float*)d_in[6];
    const float* b2        = (const float*)d_in[7];
    int n = in_sizes[0];

    static bool attr_set = false;
    if (!attr_set) {
        cudaFuncSetAttribute(neuralnet_mma16m_kernel,
                             cudaFuncAttributeMaxDynamicSharedMemorySize, SMEM_TOTAL);
        attr_set = true;
    }
    int blocks = (n + ELTS - 1) / ELTS;
    neuralnet_mma16m_kernel<<<blocks, NTHREADS, SMEM_TOTAL>>>(
        users, movies, user_emb, movie_emb, w1, b1, w2, b2, (float*)d_out, n);
}